// round 13
// baseline (speedup 1.0000x reference)
#include <cuda_runtime.h>
#include <cuda_fp16.h>
#include <math.h>
#include <stdint.h>

#define B_    32
#define C1_   128
#define C2_   128
#define KEXP_ 4
#define HH_   96
#define WW_   96
#define HW_   (HH_*WW_)
#define BHALF (B_/2)

// ---------------- scratch (device globals) -----------------------------------
__device__ float g_gate[B_*KEXP_];
__device__ float g_bmix[B_*C2_];
__device__ __half g_wh[(size_t)B_*9*C2_*C1_];       // [b][tap][c2][c1] fp16
__device__ __half g_xh[(size_t)B_*HH_*WW_*C1_];     // [b][h][w][c1]    fp16
__device__ __half g_yh[(size_t)B_*C2_*HW_];         // conv out (fp16 scratch)
__device__ float g_gpart[(size_t)B_*288*C1_];       // gap partials
__device__ float g_bnpart[(size_t)B_*24*C2_*2];     // BN partials per (b,hg)
__device__ float g_scale[C2_];
__device__ float g_shift[C2_];

// ---------------- helpers -------------------------------------------------------
__device__ __forceinline__ uint32_t smem_u32(const void* p) {
    uint32_t a;
    asm("{ .reg .u64 t; cvta.to.shared.u64 t, %1; cvt.u32.u64 %0, t; }" : "=r"(a) : "l"(p));
    return a;
}
__device__ __forceinline__ float warpReduceSum(float v) {
    #pragma unroll
    for (int o = 16; o > 0; o >>= 1) v += __shfl_down_sync(0xffffffffu, v, o);
    return v;
}
__device__ __forceinline__ void mma_f16(float* d, const uint32_t* a, const uint32_t* b) {
    asm volatile(
        "mma.sync.aligned.m16n8k16.row.col.f32.f16.f16.f32 "
        "{%0,%1,%2,%3}, {%4,%5,%6,%7}, {%8,%9}, {%0,%1,%2,%3};"
        : "+f"(d[0]), "+f"(d[1]), "+f"(d[2]), "+f"(d[3])
        : "r"(a[0]), "r"(a[1]), "r"(a[2]), "r"(a[3]), "r"(b[0]), "r"(b[1]));
}
__device__ __forceinline__ void ldsm_x4(uint32_t* r, uint32_t addr) {
    asm volatile("ldmatrix.sync.aligned.m8n8.x4.shared.b16 {%0,%1,%2,%3}, [%4];"
        : "=r"(r[0]), "=r"(r[1]), "=r"(r[2]), "=r"(r[3]) : "r"(addr));
}
__device__ __forceinline__ void ldsm_x2(uint32_t& r0, uint32_t& r1, uint32_t addr) {
    asm volatile("ldmatrix.sync.aligned.m8n8.x2.shared.b16 {%0,%1}, [%2];"
        : "=r"(r0), "=r"(r1) : "r"(addr));
}
#define CP_ASYNC16(sm, gm) asm volatile("cp.async.cg.shared.global [%0], [%1], 16;" :: "r"(sm), "l"(gm))
#define CP_COMMIT()  asm volatile("cp.async.commit_group;" ::: "memory")
#define CP_WAIT0()   asm volatile("cp.async.wait_group 0;" ::: "memory")

// ---------------- 1) x transpose + gap partials ----------------------------------
__global__ void xT_kernel(const float* __restrict__ x, int b_off) {
    __shared__ float sm[128][33];
    int wblk = blockIdx.x, h = blockIdx.y, b = blockIdx.z + b_off;
    int tid = threadIdx.x, lane = tid & 31, w = tid >> 5;
    float vals[16];
    #pragma unroll
    for (int p = 0; p < 16; p++) {
        int c1 = p*8 + w;
        float v = x[(((size_t)b*C1_ + c1)*HH_ + h)*WW_ + wblk*32 + lane];
        sm[c1][lane] = v;
        vals[p] = v;
    }
    #pragma unroll
    for (int p = 0; p < 16; p++) {
        float s = warpReduceSum(vals[p]);
        if (lane == 0)
            g_gpart[(((size_t)b*HH_ + h)*3 + wblk)*C1_ + p*8 + w] = s;
    }
    __syncthreads();
    #pragma unroll
    for (int p = 0; p < 16; p++) {
        int c1 = tid & 127;
        int j  = p*2 + (tid >> 7);
        g_xh[((((size_t)b*HH_ + h)*WW_) + wblk*32 + j)*C1_ + c1] =
            __float2half_rn(sm[c1][j]);
    }
}

// ---------------- 2) gate: gap reduce + softmax + bmix ----------------------------
__global__ void gate_kernel(const float* __restrict__ fc_w,
                            const float* __restrict__ fc_b,
                            const float* __restrict__ bias, int b_off) {
    int b = blockIdx.x + b_off;
    int tid = threadIdx.x;
    __shared__ float sgap[C1_];
    __shared__ float slog[KEXP_];
    __shared__ float sg4[KEXP_];
    float s = 0.f;
    for (int c = 0; c < 288; c++) s += g_gpart[((size_t)b*288 + c)*C1_ + tid];
    sgap[tid] = s * (1.0f / (float)HW_);
    __syncthreads();
    int k = tid >> 5, lane = tid & 31;
    float acc = 0.f;
    #pragma unroll
    for (int r = 0; r < 4; r++)
        acc += sgap[lane*4 + r] * fc_w[k*C1_ + lane*4 + r];
    acc = warpReduceSum(acc);
    if (lane == 0) slog[k] = acc + fc_b[k];
    __syncthreads();
    if (tid == 0) {
        float m = fmaxf(fmaxf(slog[0], slog[1]), fmaxf(slog[2], slog[3]));
        float e0 = expf(slog[0]-m), e1 = expf(slog[1]-m),
              e2 = expf(slog[2]-m), e3 = expf(slog[3]-m);
        float inv = 1.0f / (e0+e1+e2+e3);
        sg4[0] = e0*inv; sg4[1] = e1*inv; sg4[2] = e2*inv; sg4[3] = e3*inv;
    }
    __syncthreads();
    if (tid < KEXP_) g_gate[b*KEXP_ + tid] = sg4[tid];
    float s2 = 0.f;
    #pragma unroll
    for (int kk = 0; kk < KEXP_; kk++) s2 += sg4[kk] * bias[kk*C2_ + tid];
    g_bmix[b*C2_ + tid] = s2;
}

// ---------------- 3) weight mix (coalesced, smem-staged) ---------------------------
__global__ void wmix_kernel(const float* __restrict__ weight, int b_off) {
    __shared__ float sw[KEXP_][C1_*9];   // 18.4 KB
    __shared__ float sg[KEXP_];
    int c2 = blockIdx.x, b = blockIdx.y + b_off;
    int tid = threadIdx.x;
    if (tid < KEXP_) sg[tid] = g_gate[b*KEXP_ + tid];
    #pragma unroll
    for (int i = tid; i < KEXP_*C1_*9; i += 128) {
        int k = i / (C1_*9), off = i - k*(C1_*9);
        sw[k][off] = weight[((size_t)k*C2_ + c2)*(C1_*9) + off];
    }
    __syncthreads();
    int c1 = tid;   // 0..127
    float g0 = sg[0], g1 = sg[1], g2 = sg[2], g3 = sg[3];
    #pragma unroll
    for (int r = 0; r < 9; r++) {
        float v = g0*sw[0][c1*9 + r] + g1*sw[1][c1*9 + r]
                + g2*sw[2][c1*9 + r] + g3*sw[3][c1*9 + r];
        g_wh[(((size_t)b*9 + r)*C2_ + c2)*C1_ + c1] = __float2half_rn(v);
    }
}

// ---------------- 4) conv: 4 h-rows per CTA, ldmatrix + cp.async -------------------
#define APAD 136
#define BCOL 136
#define BROW (98*BCOL)
#define A_BYTES (128*APAD*2)            // 34816
#define B_BYTES (6*BROW*2)              // 159936
#define CONV_SMEM (2*A_BYTES + B_BYTES) // 229568 (sred aliases A buffers)

__device__ __forceinline__ void stage_A(uint32_t sa_u, const __half* wsrc, int tid) {
    #pragma unroll
    for (int p = 0; p < 8; p++) {
        int idx = p*256 + tid;
        int c2 = idx >> 4, e = idx & 15;
        CP_ASYNC16(sa_u + (uint32_t)(c2*APAD + e*8)*2,
                   wsrc + (size_t)c2*C1_ + e*8);
    }
}

__global__ void __launch_bounds__(256, 1)
conv_mma_kernel(int b_off) {
    extern __shared__ __half sh[];
    float* sred = (float*)sh;            // aliases A buffers (dead at epilogue)

    int tid = threadIdx.x, lane = tid & 31, warp = tid >> 5;
    int hg = blockIdx.x, b = blockIdx.y + b_off;
    int h0 = hg * 4;
    int i  = warp & 3;            // h row within group
    int mh = warp >> 2;           // M half
    int mbase = mh * 64;
    int gq = lane >> 2, tg = lane & 3;

    uint32_t sbase = smem_u32(sh);
    uint32_t sA_u[2] = { sbase, sbase + A_BYTES };
    uint32_t sB_u = sbase + 2*A_BYTES;
    __half* sB = (__half*)((char*)sh + 2*A_BYTES);

    // kick off A tap 0 + stage all 6 input rows
    stage_A(sA_u[0], g_wh + (size_t)b*9*C2_*C1_, tid);
    CP_COMMIT();
    {
        const __half* xb = g_xh + (size_t)b*HH_*WW_*C1_;
        for (int idx = tid; idx < 6*98*16; idx += 256) {
            int r = idx / (98*16);
            int rem = idx - r*(98*16);
            int col = rem >> 4, e = rem & 15;
            int gh = h0 - 1 + r, gw = col - 1;
            uint4 v = make_uint4(0u,0u,0u,0u);
            if ((unsigned)gh < (unsigned)HH_ && (unsigned)gw < (unsigned)WW_)
                v = *(const uint4*)(xb + ((size_t)gh*WW_ + gw)*C1_ + e*8);
            *(uint4*)(sB + r*BROW + col*BCOL + e*8) = v;
        }
    }

    float d[4][12][4];
    #pragma unroll
    for (int mi = 0; mi < 4; mi++)
        #pragma unroll
        for (int ni = 0; ni < 12; ni++)
            #pragma unroll
            for (int q = 0; q < 4; q++) d[mi][ni][q] = 0.f;

    uint32_t a_lane_off = (uint32_t)(((lane & 15)*APAD) + ((lane >> 4)*8)) * 2;
    uint32_t b_lane_off = (uint32_t)(((lane & 7)*BCOL) + (((lane >> 3) & 1)*8)) * 2;

    CP_WAIT0();
    __syncthreads();

    for (int tap = 0; tap < 9; tap++) {
        int dy = tap / 3, dx = tap - dy*3;
        int cur = tap & 1, nxt = cur ^ 1;
        if (tap < 8)
            stage_A(sA_u[nxt], g_wh + ((size_t)b*9 + tap + 1)*C2_*C1_, tid);
        CP_COMMIT();

        uint32_t abase = sA_u[cur] + (uint32_t)(mbase*APAD)*2 + a_lane_off;
        uint32_t bbase = sB_u + (uint32_t)((i + dy)*BROW + dx*BCOL)*2 + b_lane_off;

        #pragma unroll
        for (int ks = 0; ks < 8; ks++) {
            uint32_t a[4][4];
            #pragma unroll
            for (int mi = 0; mi < 4; mi++)
                ldsm_x4(a[mi], abase + mi*(16*APAD*2) + ks*32);
            #pragma unroll
            for (int ni = 0; ni < 12; ni++) {
                uint32_t bb[2];
                ldsm_x2(bb[0], bb[1], bbase + ni*(8*BCOL*2) + ks*32);
                #pragma unroll
                for (int mi = 0; mi < 4; mi++)
                    mma_f16(d[mi][ni], a[mi], bb);
            }
        }
        CP_WAIT0();
        __syncthreads();
    }

    // epilogue: +bmix, store y (fp16), BN partial sums (fp32, pre-rounding)
    int h = h0 + i;
    #pragma unroll
    for (int mi = 0; mi < 4; mi++) {
        int c2a = mbase + mi*16 + gq;
        int c2b = c2a + 8;
        float bm0 = g_bmix[b*C2_ + c2a];
        float bm1 = g_bmix[b*C2_ + c2b];
        __half* rowa = g_yh + (((size_t)b*C2_ + c2a)*HH_ + h)*WW_;
        __half* rowb = g_yh + (((size_t)b*C2_ + c2b)*HH_ + h)*WW_;
        float s0=0.f, q0=0.f, s1=0.f, q1=0.f;
        #pragma unroll
        for (int ni = 0; ni < 12; ni++) {
            int n = ni*8 + 2*tg;
            float v0 = d[mi][ni][0] + bm0, v1 = d[mi][ni][1] + bm0;
            float v2 = d[mi][ni][2] + bm1, v3 = d[mi][ni][3] + bm1;
            *(__half2*)(rowa + n) = __floats2half2_rn(v0, v1);
            *(__half2*)(rowb + n) = __floats2half2_rn(v2, v3);
            s0 += v0 + v1; q0 += v0*v0 + v1*v1;
            s1 += v2 + v3; q1 += v2*v2 + v3*v3;
        }
        s0 += __shfl_down_sync(0xffffffffu, s0, 2); s0 += __shfl_down_sync(0xffffffffu, s0, 1);
        q0 += __shfl_down_sync(0xffffffffu, q0, 2); q0 += __shfl_down_sync(0xffffffffu, q0, 1);
        s1 += __shfl_down_sync(0xffffffffu, s1, 2); s1 += __shfl_down_sync(0xffffffffu, s1, 1);
        q1 += __shfl_down_sync(0xffffffffu, q1, 2); q1 += __shfl_down_sync(0xffffffffu, q1, 1);
        if (tg == 0) {
            int base = warp*64 + mi*16;
            sred[base + gq]           = s0;
            sred[base + 8 + gq]       = s1;
            sred[512 + base + gq]     = q0;
            sred[512 + base + 8 + gq] = q1;
        }
    }
    __syncthreads();
    {
        int c2 = tid >> 1, which = tid & 1;
        int mh2 = c2 >> 6, rem = c2 & 63;
        float acc = 0.f;
        #pragma unroll
        for (int r = 0; r < 4; r++)
            acc += sred[which*512 + (mh2*4 + r)*64 + rem];
        g_bnpart[(((size_t)b*24 + hg)*C2_ + c2)*2 + which] = acc;
    }
}

// ---------------- 5) finalize BN ------------------------------------------------------
__global__ void bnfin_kernel(const float* __restrict__ gamma,
                             const float* __restrict__ beta) {
    int c2 = blockIdx.x;
    int tid = threadIdx.x;
    float s = 0.f, q = 0.f;
    for (int idx = tid; idx < B_*24; idx += 256) {
        s += g_bnpart[((size_t)idx*C2_ + c2)*2];
        q += g_bnpart[((size_t)idx*C2_ + c2)*2 + 1];
    }
    s = warpReduceSum(s); q = warpReduceSum(q);
    __shared__ float sms[8], smq[8];
    int lane = tid & 31, w = tid >> 5;
    if (lane == 0) { sms[w] = s; smq[w] = q; }
    __syncthreads();
    if (w == 0) {
        s = (lane < 8) ? sms[lane] : 0.f;
        q = (lane < 8) ? smq[lane] : 0.f;
        s = warpReduceSum(s); q = warpReduceSum(q);
        if (lane == 0) {
            const float n = (float)B_ * (float)HW_;
            float mean = s / n;
            float var  = q / n - mean*mean;
            float inv  = rsqrtf(var + 1e-5f);
            float sc = gamma[c2] * inv;
            g_scale[c2] = sc;
            g_shift[c2] = beta[c2] - mean * sc;
        }
    }
}

// ---------------- 6) BN affine + SiLU: fp16 in, fp32 out -------------------------------
__global__ void act_kernel(float* __restrict__ y) {
    int idx = blockIdx.x * 256 + threadIdx.x;   // group of 4 elements
    const int N4 = (B_*C2_*HW_) / 4;
    if (idx >= N4) return;
    int c2 = (idx / (HW_/4)) & (C2_-1);
    float sc = g_scale[c2], sh = g_shift[c2];
    uint2 raw = *(const uint2*)((const __half*)g_yh + (size_t)idx*4);
    __half2 p0 = *(__half2*)&raw.x;
    __half2 p1 = *(__half2*)&raw.y;
    float2 f0 = __half22float2(p0);
    float2 f1 = __half22float2(p1);
    float4 v;
    float t;
    t = f0.x*sc + sh; v.x = t / (1.f + expf(-t));
    t = f0.y*sc + sh; v.y = t / (1.f + expf(-t));
    t = f1.x*sc + sh; v.z = t / (1.f + expf(-t));
    t = f1.y*sc + sh; v.w = t / (1.f + expf(-t));
    ((float4*)y)[idx] = v;
}

// ---------------- launcher ---------------------------------------------------------------
extern "C" void kernel_launch(void* const* d_in, const int* in_sizes, int n_in,
                              void* d_out, int out_size) {
    const float* x      = (const float*)d_in[0];
    const float* fc_w   = (const float*)d_in[1];
    const float* fc_b   = (const float*)d_in[2];
    const float* weight = (const float*)d_in[3];
    const float* bias   = (const float*)d_in[4];
    const float* gamma  = (const float*)d_in[5];
    const float* beta   = (const float*)d_in[6];
    float* y = (float*)d_out;

    cudaFuncSetAttribute(conv_mma_kernel,
                         cudaFuncAttributeMaxDynamicSharedMemorySize, CONV_SMEM);

    // static second stream + fork/join events (created once, outside capture)
    static cudaStream_t s2 = nullptr;
    static cudaEvent_t ev_fork = nullptr, ev_join = nullptr;
    static int init_tried = 0;
    if (!init_tried) {
        init_tried = 1;
        if (cudaStreamCreateWithFlags(&s2, cudaStreamNonBlocking) != cudaSuccess)
            s2 = nullptr;
        if (s2) {
            if (cudaEventCreateWithFlags(&ev_fork, cudaEventDisableTiming) != cudaSuccess ||
                cudaEventCreateWithFlags(&ev_join, cudaEventDisableTiming) != cudaSuccess)
                s2 = nullptr;
        }
    }

    dim3 tgrid(WW_/32, HH_, BHALF);
    dim3 wgrid(C2_, BHALF);
    dim3 cgrid(24, BHALF);
    const int N4 = (B_*C2_*HW_) / 4;

    if (s2) {
        // half 1 on stream 0
        xT_kernel<<<tgrid, 256>>>(x, 0);
        cudaEventRecord(ev_fork, 0);
        // half 2 pre-work on s2, overlapping conv1
        cudaStreamWaitEvent(s2, ev_fork, 0);
        xT_kernel<<<tgrid, 256, 0, s2>>>(x, BHALF);
        gate_kernel<<<BHALF, 128, 0, s2>>>(fc_w, fc_b, bias, BHALF);
        wmix_kernel<<<wgrid, 128, 0, s2>>>(weight, BHALF);
        cudaEventRecord(ev_join, s2);
        // half 1 chain continues on stream 0
        gate_kernel<<<BHALF, 128>>>(fc_w, fc_b, bias, 0);
        wmix_kernel<<<wgrid, 128>>>(weight, 0);
        conv_mma_kernel<<<cgrid, 256, CONV_SMEM>>>(0);
        // join, then conv half 2
        cudaStreamWaitEvent(0, ev_join, 0);
        conv_mma_kernel<<<cgrid, 256, CONV_SMEM>>>(BHALF);
    } else {
        // sequential fallback
        xT_kernel<<<tgrid, 256>>>(x, 0);
        xT_kernel<<<tgrid, 256>>>(x, BHALF);
        gate_kernel<<<BHALF, 128>>>(fc_w, fc_b, bias, 0);
        gate_kernel<<<BHALF, 128>>>(fc_w, fc_b, bias, BHALF);
        wmix_kernel<<<wgrid, 128>>>(weight, 0);
        wmix_kernel<<<wgrid, 128>>>(weight, BHALF);
        conv_mma_kernel<<<cgrid, 256, CONV_SMEM>>>(0);
        conv_mma_kernel<<<cgrid, 256, CONV_SMEM>>>(BHALF);
    }

    bnfin_kernel<<<C2_, 256>>>(gamma, beta);
    act_kernel<<<(N4 + 255)/256, 256>>>(y);
}

// round 14
// speedup vs baseline: 1.0369x; 1.0369x over previous
#include <cuda_runtime.h>
#include <cuda_fp16.h>
#include <math.h>
#include <stdint.h>

#define B_    32
#define C1_   128
#define C2_   128
#define KEXP_ 4
#define HH_   96
#define WW_   96
#define HW_   (HH_*WW_)

// ---------------- scratch (device globals) -----------------------------------
__device__ float g_gate[B_*KEXP_];
__device__ float g_bmix[B_*C2_];
__device__ __half g_wh[(size_t)B_*9*C2_*C1_];       // [b][tap][c2][c1] fp16
__device__ __half g_xh[(size_t)B_*HH_*WW_*C1_];     // [b][h][w][c1]    fp16
__device__ __half g_yh[(size_t)B_*C2_*HW_];         // conv out (fp16 scratch)
__device__ float g_gpart[(size_t)B_*288*C1_];       // gap partials
__device__ float g_bnpart[(size_t)B_*24*C2_*2];     // BN partials per (b,hg)
__device__ float g_scale[C2_];
__device__ float g_shift[C2_];

// ---------------- helpers -------------------------------------------------------
__device__ __forceinline__ uint32_t smem_u32(const void* p) {
    uint32_t a;
    asm("{ .reg .u64 t; cvta.to.shared.u64 t, %1; cvt.u32.u64 %0, t; }" : "=r"(a) : "l"(p));
    return a;
}
__device__ __forceinline__ float warpReduceSum(float v) {
    #pragma unroll
    for (int o = 16; o > 0; o >>= 1) v += __shfl_down_sync(0xffffffffu, v, o);
    return v;
}
__device__ __forceinline__ void mma_f16(float* d, const uint32_t* a, const uint32_t* b) {
    asm volatile(
        "mma.sync.aligned.m16n8k16.row.col.f32.f16.f16.f32 "
        "{%0,%1,%2,%3}, {%4,%5,%6,%7}, {%8,%9}, {%0,%1,%2,%3};"
        : "+f"(d[0]), "+f"(d[1]), "+f"(d[2]), "+f"(d[3])
        : "r"(a[0]), "r"(a[1]), "r"(a[2]), "r"(a[3]), "r"(b[0]), "r"(b[1]));
}
__device__ __forceinline__ void ldsm_x4(uint32_t* r, uint32_t addr) {
    asm volatile("ldmatrix.sync.aligned.m8n8.x4.shared.b16 {%0,%1,%2,%3}, [%4];"
        : "=r"(r[0]), "=r"(r[1]), "=r"(r[2]), "=r"(r[3]) : "r"(addr));
}
__device__ __forceinline__ void ldsm_x2(uint32_t& r0, uint32_t& r1, uint32_t addr) {
    asm volatile("ldmatrix.sync.aligned.m8n8.x2.shared.b16 {%0,%1}, [%2];"
        : "=r"(r0), "=r"(r1) : "r"(addr));
}
#define CP_ASYNC16(sm, gm) asm volatile("cp.async.cg.shared.global [%0], [%1], 16;" :: "r"(sm), "l"(gm))
#define CP_COMMIT()  asm volatile("cp.async.commit_group;" ::: "memory")
#define CP_WAIT0()   asm volatile("cp.async.wait_group 0;" ::: "memory")

// ---------------- 1) x transpose + gap partials ----------------------------------
__global__ void xT_kernel(const float* __restrict__ x) {
    __shared__ float sm[128][33];
    int wblk = blockIdx.x, h = blockIdx.y, b = blockIdx.z;
    int tid = threadIdx.x, lane = tid & 31, w = tid >> 5;
    float vals[16];
    #pragma unroll
    for (int p = 0; p < 16; p++) {
        int c1 = p*8 + w;
        float v = x[(((size_t)b*C1_ + c1)*HH_ + h)*WW_ + wblk*32 + lane];
        sm[c1][lane] = v;
        vals[p] = v;
    }
    #pragma unroll
    for (int p = 0; p < 16; p++) {
        float s = warpReduceSum(vals[p]);
        if (lane == 0)
            g_gpart[(((size_t)b*HH_ + h)*3 + wblk)*C1_ + p*8 + w] = s;
    }
    __syncthreads();
    #pragma unroll
    for (int p = 0; p < 16; p++) {
        int c1 = tid & 127;
        int j  = p*2 + (tid >> 7);
        g_xh[((((size_t)b*HH_ + h)*WW_) + wblk*32 + j)*C1_ + c1] =
            __float2half_rn(sm[c1][j]);
    }
}

// ---------------- 2) gate: gap reduce + softmax + bmix ----------------------------
__global__ void gate_kernel(const float* __restrict__ fc_w,
                            const float* __restrict__ fc_b,
                            const float* __restrict__ bias) {
    int b = blockIdx.x;
    int tid = threadIdx.x;
    __shared__ float sgap[C1_];
    __shared__ float slog[KEXP_];
    __shared__ float sg4[KEXP_];
    float s = 0.f;
    for (int c = 0; c < 288; c++) s += g_gpart[((size_t)b*288 + c)*C1_ + tid];
    sgap[tid] = s * (1.0f / (float)HW_);
    __syncthreads();
    int k = tid >> 5, lane = tid & 31;
    float acc = 0.f;
    #pragma unroll
    for (int r = 0; r < 4; r++)
        acc += sgap[lane*4 + r] * fc_w[k*C1_ + lane*4 + r];
    acc = warpReduceSum(acc);
    if (lane == 0) slog[k] = acc + fc_b[k];
    __syncthreads();
    if (tid == 0) {
        float m = fmaxf(fmaxf(slog[0], slog[1]), fmaxf(slog[2], slog[3]));
        float e0 = expf(slog[0]-m), e1 = expf(slog[1]-m),
              e2 = expf(slog[2]-m), e3 = expf(slog[3]-m);
        float inv = 1.0f / (e0+e1+e2+e3);
        sg4[0] = e0*inv; sg4[1] = e1*inv; sg4[2] = e2*inv; sg4[3] = e3*inv;
    }
    __syncthreads();
    if (tid < KEXP_) g_gate[b*KEXP_ + tid] = sg4[tid];
    float s2 = 0.f;
    #pragma unroll
    for (int kk = 0; kk < KEXP_; kk++) s2 += sg4[kk] * bias[kk*C2_ + tid];
    g_bmix[b*C2_ + tid] = s2;
}

// ---------------- 3) weight mix: one block per c2, loop over b ----------------------
__global__ void wmix_kernel(const float* __restrict__ weight) {
    __shared__ float sw[KEXP_][C1_*9];   // 18.4 KB, staged once per c2
    int c2 = blockIdx.x;
    int tid = threadIdx.x;               // 256 threads
    for (int i = tid; i < KEXP_*C1_*9; i += 256) {
        int k = i / (C1_*9), off = i - k*(C1_*9);
        sw[k][off] = weight[((size_t)k*C2_ + c2)*(C1_*9) + off];
    }
    __syncthreads();
    int c1 = tid & 127;
    for (int b = tid >> 7; b < B_; b += 2) {
        float g0 = g_gate[b*KEXP_ + 0], g1 = g_gate[b*KEXP_ + 1];
        float g2 = g_gate[b*KEXP_ + 2], g3 = g_gate[b*KEXP_ + 3];
        #pragma unroll
        for (int r = 0; r < 9; r++) {
            float v = g0*sw[0][c1*9 + r] + g1*sw[1][c1*9 + r]
                    + g2*sw[2][c1*9 + r] + g3*sw[3][c1*9 + r];
            g_wh[(((size_t)b*9 + r)*C2_ + c2)*C1_ + c1] = __float2half_rn(v);
        }
    }
}

// ---------------- 4) conv: 4 h-rows per CTA, ldmatrix + cp.async -------------------
#define APAD 136
#define BCOL 136
#define BROW (98*BCOL)
#define A_BYTES (128*APAD*2)            // 34816
#define B_BYTES (6*BROW*2)              // 159936
#define CONV_SMEM (2*A_BYTES + B_BYTES) // 229568 (sred aliases A buffers)

__device__ __forceinline__ void stage_A(uint32_t sa_u, const __half* wsrc, int tid) {
    #pragma unroll
    for (int p = 0; p < 8; p++) {
        int idx = p*256 + tid;
        int c2 = idx >> 4, e = idx & 15;
        CP_ASYNC16(sa_u + (uint32_t)(c2*APAD + e*8)*2,
                   wsrc + (size_t)c2*C1_ + e*8);
    }
}

__global__ void __launch_bounds__(256, 1)
conv_mma_kernel() {
    extern __shared__ __half sh[];
    float* sred = (float*)sh;            // aliases A buffers (dead at epilogue)

    int tid = threadIdx.x, lane = tid & 31, warp = tid >> 5;
    int hg = blockIdx.x, b = blockIdx.y;
    int h0 = hg * 4;
    int i  = warp & 3;            // h row within group
    int mh = warp >> 2;           // M half
    int mbase = mh * 64;
    int gq = lane >> 2, tg = lane & 3;

    uint32_t sbase = smem_u32(sh);
    uint32_t sA_u[2] = { sbase, sbase + A_BYTES };
    uint32_t sB_u = sbase + 2*A_BYTES;
    __half* sB = (__half*)((char*)sh + 2*A_BYTES);

    // kick off A tap 0 + stage all 6 input rows
    stage_A(sA_u[0], g_wh + (size_t)b*9*C2_*C1_, tid);
    CP_COMMIT();
    {
        const __half* xb = g_xh + (size_t)b*HH_*WW_*C1_;
        for (int idx = tid; idx < 6*98*16; idx += 256) {
            int r = idx / (98*16);
            int rem = idx - r*(98*16);
            int col = rem >> 4, e = rem & 15;
            int gh = h0 - 1 + r, gw = col - 1;
            uint4 v = make_uint4(0u,0u,0u,0u);
            if ((unsigned)gh < (unsigned)HH_ && (unsigned)gw < (unsigned)WW_)
                v = *(const uint4*)(xb + ((size_t)gh*WW_ + gw)*C1_ + e*8);
            *(uint4*)(sB + r*BROW + col*BCOL + e*8) = v;
        }
    }

    float d[4][12][4];
    #pragma unroll
    for (int mi = 0; mi < 4; mi++)
        #pragma unroll
        for (int ni = 0; ni < 12; ni++)
            #pragma unroll
            for (int q = 0; q < 4; q++) d[mi][ni][q] = 0.f;

    uint32_t a_lane_off = (uint32_t)(((lane & 15)*APAD) + ((lane >> 4)*8)) * 2;
    uint32_t b_lane_off = (uint32_t)(((lane & 7)*BCOL) + (((lane >> 3) & 1)*8)) * 2;

    CP_WAIT0();
    __syncthreads();

    for (int tap = 0; tap < 9; tap++) {
        int dy = tap / 3, dx = tap - dy*3;
        int cur = tap & 1, nxt = cur ^ 1;
        if (tap < 8)
            stage_A(sA_u[nxt], g_wh + ((size_t)b*9 + tap + 1)*C2_*C1_, tid);
        CP_COMMIT();

        uint32_t abase = sA_u[cur] + (uint32_t)(mbase*APAD)*2 + a_lane_off;
        uint32_t bbase = sB_u + (uint32_t)((i + dy)*BROW + dx*BCOL)*2 + b_lane_off;

        #pragma unroll
        for (int ks = 0; ks < 8; ks++) {
            uint32_t a[4][4];
            #pragma unroll
            for (int mi = 0; mi < 4; mi++)
                ldsm_x4(a[mi], abase + mi*(16*APAD*2) + ks*32);
            #pragma unroll
            for (int ni = 0; ni < 12; ni++) {
                uint32_t bb[2];
                ldsm_x2(bb[0], bb[1], bbase + ni*(8*BCOL*2) + ks*32);
                #pragma unroll
                for (int mi = 0; mi < 4; mi++)
                    mma_f16(d[mi][ni], a[mi], bb);
            }
        }
        CP_WAIT0();
        __syncthreads();
    }

    // epilogue: +bmix, store y (fp16), BN partial sums (fp32, pre-rounding)
    int h = h0 + i;
    #pragma unroll
    for (int mi = 0; mi < 4; mi++) {
        int c2a = mbase + mi*16 + gq;
        int c2b = c2a + 8;
        float bm0 = g_bmix[b*C2_ + c2a];
        float bm1 = g_bmix[b*C2_ + c2b];
        __half* rowa = g_yh + (((size_t)b*C2_ + c2a)*HH_ + h)*WW_;
        __half* rowb = g_yh + (((size_t)b*C2_ + c2b)*HH_ + h)*WW_;
        float s0=0.f, q0=0.f, s1=0.f, q1=0.f;
        #pragma unroll
        for (int ni = 0; ni < 12; ni++) {
            int n = ni*8 + 2*tg;
            float v0 = d[mi][ni][0] + bm0, v1 = d[mi][ni][1] + bm0;
            float v2 = d[mi][ni][2] + bm1, v3 = d[mi][ni][3] + bm1;
            *(__half2*)(rowa + n) = __floats2half2_rn(v0, v1);
            *(__half2*)(rowb + n) = __floats2half2_rn(v2, v3);
            s0 += v0 + v1; q0 += v0*v0 + v1*v1;
            s1 += v2 + v3; q1 += v2*v2 + v3*v3;
        }
        s0 += __shfl_down_sync(0xffffffffu, s0, 2); s0 += __shfl_down_sync(0xffffffffu, s0, 1);
        q0 += __shfl_down_sync(0xffffffffu, q0, 2); q0 += __shfl_down_sync(0xffffffffu, q0, 1);
        s1 += __shfl_down_sync(0xffffffffu, s1, 2); s1 += __shfl_down_sync(0xffffffffu, s1, 1);
        q1 += __shfl_down_sync(0xffffffffu, q1, 2); q1 += __shfl_down_sync(0xffffffffu, q1, 1);
        if (tg == 0) {
            int base = warp*64 + mi*16;
            sred[base + gq]           = s0;
            sred[base + 8 + gq]       = s1;
            sred[512 + base + gq]     = q0;
            sred[512 + base + 8 + gq] = q1;
        }
    }
    __syncthreads();
    {
        int c2 = tid >> 1, which = tid & 1;
        int mh2 = c2 >> 6, rem = c2 & 63;
        float acc = 0.f;
        #pragma unroll
        for (int r = 0; r < 4; r++)
            acc += sred[which*512 + (mh2*4 + r)*64 + rem];
        g_bnpart[(((size_t)b*24 + hg)*C2_ + c2)*2 + which] = acc;
    }
}

// ---------------- 5) finalize BN ------------------------------------------------------
__global__ void bnfin_kernel(const float* __restrict__ gamma,
                             const float* __restrict__ beta) {
    int c2 = blockIdx.x;
    int tid = threadIdx.x;
    float s = 0.f, q = 0.f;
    for (int idx = tid; idx < B_*24; idx += 256) {
        s += g_bnpart[((size_t)idx*C2_ + c2)*2];
        q += g_bnpart[((size_t)idx*C2_ + c2)*2 + 1];
    }
    s = warpReduceSum(s); q = warpReduceSum(q);
    __shared__ float sms[8], smq[8];
    int lane = tid & 31, w = tid >> 5;
    if (lane == 0) { sms[w] = s; smq[w] = q; }
    __syncthreads();
    if (w == 0) {
        s = (lane < 8) ? sms[lane] : 0.f;
        q = (lane < 8) ? smq[lane] : 0.f;
        s = warpReduceSum(s); q = warpReduceSum(q);
        if (lane == 0) {
            const float n = (float)B_ * (float)HW_;
            float mean = s / n;
            float var  = q / n - mean*mean;
            float inv  = rsqrtf(var + 1e-5f);
            float sc = gamma[c2] * inv;
            g_scale[c2] = sc;
            g_shift[c2] = beta[c2] - mean * sc;
        }
    }
}

// ---------------- 6) BN affine + SiLU: fp16 in, fp32 out, 8 elems/thread ---------------
__global__ void act_kernel(float* __restrict__ y) {
    int idx = blockIdx.x * 256 + threadIdx.x;   // group of 8 elements
    const int N8 = (B_*C2_*HW_) / 8;
    if (idx >= N8) return;
    int c2 = (idx / (HW_/8)) & (C2_-1);
    float sc = g_scale[c2], sh = g_shift[c2];
    uint4 raw = *(const uint4*)((const __half*)g_yh + (size_t)idx*8);
    __half2 p0 = *(__half2*)&raw.x, p1 = *(__half2*)&raw.y;
    __half2 p2 = *(__half2*)&raw.z, p3 = *(__half2*)&raw.w;
    float2 f0 = __half22float2(p0), f1 = __half22float2(p1);
    float2 f2 = __half22float2(p2), f3 = __half22float2(p3);
    float4 v0, v1;
    float t;
    t = f0.x*sc + sh; v0.x = t / (1.f + expf(-t));
    t = f0.y*sc + sh; v0.y = t / (1.f + expf(-t));
    t = f1.x*sc + sh; v0.z = t / (1.f + expf(-t));
    t = f1.y*sc + sh; v0.w = t / (1.f + expf(-t));
    t = f2.x*sc + sh; v1.x = t / (1.f + expf(-t));
    t = f2.y*sc + sh; v1.y = t / (1.f + expf(-t));
    t = f3.x*sc + sh; v1.z = t / (1.f + expf(-t));
    t = f3.y*sc + sh; v1.w = t / (1.f + expf(-t));
    ((float4*)y)[idx*2]     = v0;
    ((float4*)y)[idx*2 + 1] = v1;
}

// ---------------- launcher ---------------------------------------------------------------
extern "C" void kernel_launch(void* const* d_in, const int* in_sizes, int n_in,
                              void* d_out, int out_size) {
    const float* x      = (const float*)d_in[0];
    const float* fc_w   = (const float*)d_in[1];
    const float* fc_b   = (const float*)d_in[2];
    const float* weight = (const float*)d_in[3];
    const float* bias   = (const float*)d_in[4];
    const float* gamma  = (const float*)d_in[5];
    const float* beta   = (const float*)d_in[6];
    float* y = (float*)d_out;

    cudaFuncSetAttribute(conv_mma_kernel,
                         cudaFuncAttributeMaxDynamicSharedMemorySize, CONV_SMEM);

    dim3 tgrid(WW_/32, HH_, B_);
    xT_kernel<<<tgrid, 256>>>(x);

    gate_kernel<<<B_, 128>>>(fc_w, fc_b, bias);

    wmix_kernel<<<C2_, 256>>>(weight);

    dim3 cgrid(24, B_);
    conv_mma_kernel<<<cgrid, 256, CONV_SMEM>>>();

    bnfin_kernel<<<C2_, 256>>>(gamma, beta);

    const int N8 = (B_*C2_*HW_) / 8;
    act_kernel<<<(N8 + 255)/256, 256>>>(y);
}

// round 15
// speedup vs baseline: 1.0395x; 1.0026x over previous
#include <cuda_runtime.h>
#include <cuda_fp16.h>
#include <math.h>
#include <stdint.h>

#define B_    32
#define C1_   128
#define C2_   128
#define KEXP_ 4
#define HH_   96
#define WW_   96
#define HW_   (HH_*WW_)

// ---------------- scratch (device globals) -----------------------------------
__device__ float g_gate[B_*KEXP_];
__device__ float g_bmix[B_*C2_];
__device__ __half g_wh[(size_t)B_*9*C2_*C1_];       // [b][tap][c2][c1] fp16
__device__ __half g_xh[(size_t)B_*HH_*WW_*C1_];     // [b][h][w][c1]    fp16
__device__ __half g_yh[(size_t)B_*C2_*HW_];         // conv out (fp16 scratch)
__device__ float g_gpart[(size_t)B_*288*C1_];       // gap partials
__device__ float g_bnpart[(size_t)B_*24*C2_*2];     // BN partials per (b,hg)
__device__ float g_scale[C2_];
__device__ float g_shift[C2_];
__device__ int   g_cnt[B_];                          // xT completion counters (init 0)

// ---------------- helpers -------------------------------------------------------
__device__ __forceinline__ uint32_t smem_u32(const void* p) {
    uint32_t a;
    asm("{ .reg .u64 t; cvta.to.shared.u64 t, %1; cvt.u32.u64 %0, t; }" : "=r"(a) : "l"(p));
    return a;
}
__device__ __forceinline__ float warpReduceSum(float v) {
    #pragma unroll
    for (int o = 16; o > 0; o >>= 1) v += __shfl_down_sync(0xffffffffu, v, o);
    return v;
}
__device__ __forceinline__ void mma_f16(float* d, const uint32_t* a, const uint32_t* b) {
    asm volatile(
        "mma.sync.aligned.m16n8k16.row.col.f32.f16.f16.f32 "
        "{%0,%1,%2,%3}, {%4,%5,%6,%7}, {%8,%9}, {%0,%1,%2,%3};"
        : "+f"(d[0]), "+f"(d[1]), "+f"(d[2]), "+f"(d[3])
        : "r"(a[0]), "r"(a[1]), "r"(a[2]), "r"(a[3]), "r"(b[0]), "r"(b[1]));
}
__device__ __forceinline__ void ldsm_x4(uint32_t* r, uint32_t addr) {
    asm volatile("ldmatrix.sync.aligned.m8n8.x4.shared.b16 {%0,%1,%2,%3}, [%4];"
        : "=r"(r[0]), "=r"(r[1]), "=r"(r[2]), "=r"(r[3]) : "r"(addr));
}
__device__ __forceinline__ void ldsm_x2(uint32_t& r0, uint32_t& r1, uint32_t addr) {
    asm volatile("ldmatrix.sync.aligned.m8n8.x2.shared.b16 {%0,%1}, [%2];"
        : "=r"(r0), "=r"(r1) : "r"(addr));
}
#define CP_ASYNC16(sm, gm) asm volatile("cp.async.cg.shared.global [%0], [%1], 16;" :: "r"(sm), "l"(gm))
#define CP_COMMIT()  asm volatile("cp.async.commit_group;" ::: "memory")
#define CP_WAIT0()   asm volatile("cp.async.wait_group 0;" ::: "memory")

// ---------------- 1) x transpose + gap partials + FUSED gate (last block per b) ----
__global__ void xT_kernel(const float* __restrict__ x,
                          const float* __restrict__ fc_w,
                          const float* __restrict__ fc_b,
                          const float* __restrict__ bias) {
    __shared__ float sm[128][33];
    int wblk = blockIdx.x, h = blockIdx.y, b = blockIdx.z;
    int tid = threadIdx.x, lane = tid & 31, w = tid >> 5;
    float vals[16];
    #pragma unroll
    for (int p = 0; p < 16; p++) {
        int c1 = p*8 + w;
        float v = x[(((size_t)b*C1_ + c1)*HH_ + h)*WW_ + wblk*32 + lane];
        sm[c1][lane] = v;
        vals[p] = v;
    }
    #pragma unroll
    for (int p = 0; p < 16; p++) {
        float s = warpReduceSum(vals[p]);
        if (lane == 0)
            g_gpart[(((size_t)b*HH_ + h)*3 + wblk)*C1_ + p*8 + w] = s;
    }
    __syncthreads();
    #pragma unroll
    for (int p = 0; p < 16; p++) {
        int c1 = tid & 127;
        int j  = p*2 + (tid >> 7);
        g_xh[((((size_t)b*HH_ + h)*WW_) + wblk*32 + j)*C1_ + c1] =
            __float2half_rn(sm[c1][j]);
    }

    // ---- last-block-per-b gate computation (threadfence reduction pattern) ----
    __shared__ int s_last;
    __threadfence();
    if (tid == 0) {
        int old = atomicAdd(&g_cnt[b], 1);
        s_last = (old == 287);
        if (s_last) g_cnt[b] = 0;       // reset for next graph replay
    }
    __syncthreads();
    if (!s_last) return;

    __shared__ float stmp[256];
    __shared__ float sgap[C1_];
    __shared__ float slog[KEXP_];
    __shared__ float sg4[KEXP_];
    {
        int c1 = tid & 127, half = tid >> 7;
        float s = 0.f;
        for (int c = half; c < 288; c += 2)
            s += g_gpart[((size_t)b*288 + c)*C1_ + c1];
        stmp[tid] = s;
    }
    __syncthreads();
    if (tid < 128) sgap[tid] = (stmp[tid] + stmp[tid + 128]) * (1.0f / (float)HW_);
    __syncthreads();
    if (tid < 128) {
        int k = tid >> 5, lane2 = tid & 31;
        float acc = 0.f;
        #pragma unroll
        for (int r = 0; r < 4; r++)
            acc += sgap[lane2*4 + r] * fc_w[k*C1_ + lane2*4 + r];
        acc = warpReduceSum(acc);
        if (lane2 == 0) slog[k] = acc + fc_b[k];
    }
    __syncthreads();
    if (tid == 0) {
        float m = fmaxf(fmaxf(slog[0], slog[1]), fmaxf(slog[2], slog[3]));
        float e0 = expf(slog[0]-m), e1 = expf(slog[1]-m),
              e2 = expf(slog[2]-m), e3 = expf(slog[3]-m);
        float inv = 1.0f / (e0+e1+e2+e3);
        sg4[0] = e0*inv; sg4[1] = e1*inv; sg4[2] = e2*inv; sg4[3] = e3*inv;
    }
    __syncthreads();
    if (tid < KEXP_) g_gate[b*KEXP_ + tid] = sg4[tid];
    if (tid < 128) {
        float s2 = 0.f;
        #pragma unroll
        for (int kk = 0; kk < KEXP_; kk++) s2 += sg4[kk] * bias[kk*C2_ + tid];
        g_bmix[b*C2_ + tid] = s2;
    }
}

// ---------------- 2) weight mix: one block per c2, loop over b ----------------------
__global__ void wmix_kernel(const float* __restrict__ weight) {
    __shared__ float sw[KEXP_][C1_*9];   // 18.4 KB, staged once per c2
    int c2 = blockIdx.x;
    int tid = threadIdx.x;               // 256 threads
    for (int i = tid; i < KEXP_*C1_*9; i += 256) {
        int k = i / (C1_*9), off = i - k*(C1_*9);
        sw[k][off] = weight[((size_t)k*C2_ + c2)*(C1_*9) + off];
    }
    __syncthreads();
    int c1 = tid & 127;
    for (int b = tid >> 7; b < B_; b += 2) {
        float g0 = g_gate[b*KEXP_ + 0], g1 = g_gate[b*KEXP_ + 1];
        float g2 = g_gate[b*KEXP_ + 2], g3 = g_gate[b*KEXP_ + 3];
        #pragma unroll
        for (int r = 0; r < 9; r++) {
            float v = g0*sw[0][c1*9 + r] + g1*sw[1][c1*9 + r]
                    + g2*sw[2][c1*9 + r] + g3*sw[3][c1*9 + r];
            g_wh[(((size_t)b*9 + r)*C2_ + c2)*C1_ + c1] = __float2half_rn(v);
        }
    }
}

// ---------------- 3) conv: 4 h-rows per CTA, ldmatrix + cp.async -------------------
#define APAD 136
#define BCOL 136
#define BROW (98*BCOL)
#define A_BYTES (128*APAD*2)            // 34816
#define B_BYTES (6*BROW*2)              // 159936
#define CONV_SMEM (2*A_BYTES + B_BYTES) // 229568 (sred aliases A buffers)

__device__ __forceinline__ void stage_A(uint32_t sa_u, const __half* wsrc, int tid) {
    #pragma unroll
    for (int p = 0; p < 8; p++) {
        int idx = p*256 + tid;
        int c2 = idx >> 4, e = idx & 15;
        CP_ASYNC16(sa_u + (uint32_t)(c2*APAD + e*8)*2,
                   wsrc + (size_t)c2*C1_ + e*8);
    }
}

__global__ void __launch_bounds__(256, 1)
conv_mma_kernel() {
    extern __shared__ __half sh[];
    float* sred = (float*)sh;            // aliases A buffers (dead at epilogue)

    int tid = threadIdx.x, lane = tid & 31, warp = tid >> 5;
    int hg = blockIdx.x, b = blockIdx.y;
    int h0 = hg * 4;
    int i  = warp & 3;            // h row within group
    int mh = warp >> 2;           // M half
    int mbase = mh * 64;
    int gq = lane >> 2, tg = lane & 3;

    uint32_t sbase = smem_u32(sh);
    uint32_t sA_u[2] = { sbase, sbase + A_BYTES };
    uint32_t sB_u = sbase + 2*A_BYTES;
    __half* sB = (__half*)((char*)sh + 2*A_BYTES);

    // kick off A tap 0 + stage all 6 input rows
    stage_A(sA_u[0], g_wh + (size_t)b*9*C2_*C1_, tid);
    CP_COMMIT();
    {
        const __half* xb = g_xh + (size_t)b*HH_*WW_*C1_;
        for (int idx = tid; idx < 6*98*16; idx += 256) {
            int r = idx / (98*16);
            int rem = idx - r*(98*16);
            int col = rem >> 4, e = rem & 15;
            int gh = h0 - 1 + r, gw = col - 1;
            uint4 v = make_uint4(0u,0u,0u,0u);
            if ((unsigned)gh < (unsigned)HH_ && (unsigned)gw < (unsigned)WW_)
                v = *(const uint4*)(xb + ((size_t)gh*WW_ + gw)*C1_ + e*8);
            *(uint4*)(sB + r*BROW + col*BCOL + e*8) = v;
        }
    }

    float d[4][12][4];
    #pragma unroll
    for (int mi = 0; mi < 4; mi++)
        #pragma unroll
        for (int ni = 0; ni < 12; ni++)
            #pragma unroll
            for (int q = 0; q < 4; q++) d[mi][ni][q] = 0.f;

    uint32_t a_lane_off = (uint32_t)(((lane & 15)*APAD) + ((lane >> 4)*8)) * 2;
    uint32_t b_lane_off = (uint32_t)(((lane & 7)*BCOL) + (((lane >> 3) & 1)*8)) * 2;

    CP_WAIT0();
    __syncthreads();

    for (int tap = 0; tap < 9; tap++) {
        int dy = tap / 3, dx = tap - dy*3;
        int cur = tap & 1, nxt = cur ^ 1;
        if (tap < 8)
            stage_A(sA_u[nxt], g_wh + ((size_t)b*9 + tap + 1)*C2_*C1_, tid);
        CP_COMMIT();

        uint32_t abase = sA_u[cur] + (uint32_t)(mbase*APAD)*2 + a_lane_off;
        uint32_t bbase = sB_u + (uint32_t)((i + dy)*BROW + dx*BCOL)*2 + b_lane_off;

        #pragma unroll
        for (int ks = 0; ks < 8; ks++) {
            uint32_t a[4][4];
            #pragma unroll
            for (int mi = 0; mi < 4; mi++)
                ldsm_x4(a[mi], abase + mi*(16*APAD*2) + ks*32);
            #pragma unroll
            for (int ni = 0; ni < 12; ni++) {
                uint32_t bb[2];
                ldsm_x2(bb[0], bb[1], bbase + ni*(8*BCOL*2) + ks*32);
                #pragma unroll
                for (int mi = 0; mi < 4; mi++)
                    mma_f16(d[mi][ni], a[mi], bb);
            }
        }
        CP_WAIT0();
        __syncthreads();
    }

    // epilogue: +bmix, store y (fp16), BN partial sums (fp32, pre-rounding)
    int h = h0 + i;
    #pragma unroll
    for (int mi = 0; mi < 4; mi++) {
        int c2a = mbase + mi*16 + gq;
        int c2b = c2a + 8;
        float bm0 = g_bmix[b*C2_ + c2a];
        float bm1 = g_bmix[b*C2_ + c2b];
        __half* rowa = g_yh + (((size_t)b*C2_ + c2a)*HH_ + h)*WW_;
        __half* rowb = g_yh + (((size_t)b*C2_ + c2b)*HH_ + h)*WW_;
        float s0=0.f, q0=0.f, s1=0.f, q1=0.f;
        #pragma unroll
        for (int ni = 0; ni < 12; ni++) {
            int n = ni*8 + 2*tg;
            float v0 = d[mi][ni][0] + bm0, v1 = d[mi][ni][1] + bm0;
            float v2 = d[mi][ni][2] + bm1, v3 = d[mi][ni][3] + bm1;
            *(__half2*)(rowa + n) = __floats2half2_rn(v0, v1);
            *(__half2*)(rowb + n) = __floats2half2_rn(v2, v3);
            s0 += v0 + v1; q0 += v0*v0 + v1*v1;
            s1 += v2 + v3; q1 += v2*v2 + v3*v3;
        }
        s0 += __shfl_down_sync(0xffffffffu, s0, 2); s0 += __shfl_down_sync(0xffffffffu, s0, 1);
        q0 += __shfl_down_sync(0xffffffffu, q0, 2); q0 += __shfl_down_sync(0xffffffffu, q0, 1);
        s1 += __shfl_down_sync(0xffffffffu, s1, 2); s1 += __shfl_down_sync(0xffffffffu, s1, 1);
        q1 += __shfl_down_sync(0xffffffffu, q1, 2); q1 += __shfl_down_sync(0xffffffffu, q1, 1);
        if (tg == 0) {
            int base = warp*64 + mi*16;
            sred[base + gq]           = s0;
            sred[base + 8 + gq]       = s1;
            sred[512 + base + gq]     = q0;
            sred[512 + base + 8 + gq] = q1;
        }
    }
    __syncthreads();
    {
        int c2 = tid >> 1, which = tid & 1;
        int mh2 = c2 >> 6, rem = c2 & 63;
        float acc = 0.f;
        #pragma unroll
        for (int r = 0; r < 4; r++)
            acc += sred[which*512 + (mh2*4 + r)*64 + rem];
        g_bnpart[(((size_t)b*24 + hg)*C2_ + c2)*2 + which] = acc;
    }
}

// ---------------- 4) finalize BN ------------------------------------------------------
__global__ void bnfin_kernel(const float* __restrict__ gamma,
                             const float* __restrict__ beta) {
    int c2 = blockIdx.x;
    int tid = threadIdx.x;
    float s = 0.f, q = 0.f;
    for (int idx = tid; idx < B_*24; idx += 256) {
        s += g_bnpart[((size_t)idx*C2_ + c2)*2];
        q += g_bnpart[((size_t)idx*C2_ + c2)*2 + 1];
    }
    s = warpReduceSum(s); q = warpReduceSum(q);
    __shared__ float sms[8], smq[8];
    int lane = tid & 31, w = tid >> 5;
    if (lane == 0) { sms[w] = s; smq[w] = q; }
    __syncthreads();
    if (w == 0) {
        s = (lane < 8) ? sms[lane] : 0.f;
        q = (lane < 8) ? smq[lane] : 0.f;
        s = warpReduceSum(s); q = warpReduceSum(q);
        if (lane == 0) {
            const float n = (float)B_ * (float)HW_;
            float mean = s / n;
            float var  = q / n - mean*mean;
            float inv  = rsqrtf(var + 1e-5f);
            float sc = gamma[c2] * inv;
            g_scale[c2] = sc;
            g_shift[c2] = beta[c2] - mean * sc;
        }
    }
}

// ---------------- 5) BN affine + SiLU: fp16 in, fp32 out, 8 elems/thread ---------------
__global__ void act_kernel(float* __restrict__ y) {
    int idx = blockIdx.x * 256 + threadIdx.x;   // group of 8 elements
    const int N8 = (B_*C2_*HW_) / 8;
    if (idx >= N8) return;
    int c2 = (idx / (HW_/8)) & (C2_-1);
    float sc = g_scale[c2], sh = g_shift[c2];
    uint4 raw = *(const uint4*)((const __half*)g_yh + (size_t)idx*8);
    __half2 p0 = *(__half2*)&raw.x, p1 = *(__half2*)&raw.y;
    __half2 p2 = *(__half2*)&raw.z, p3 = *(__half2*)&raw.w;
    float2 f0 = __half22float2(p0), f1 = __half22float2(p1);
    float2 f2 = __half22float2(p2), f3 = __half22float2(p3);
    float4 v0, v1;
    float t;
    t = f0.x*sc + sh; v0.x = t / (1.f + expf(-t));
    t = f0.y*sc + sh; v0.y = t / (1.f + expf(-t));
    t = f1.x*sc + sh; v0.z = t / (1.f + expf(-t));
    t = f1.y*sc + sh; v0.w = t / (1.f + expf(-t));
    t = f2.x*sc + sh; v1.x = t / (1.f + expf(-t));
    t = f2.y*sc + sh; v1.y = t / (1.f + expf(-t));
    t = f3.x*sc + sh; v1.z = t / (1.f + expf(-t));
    t = f3.y*sc + sh; v1.w = t / (1.f + expf(-t));
    ((float4*)y)[idx*2]     = v0;
    ((float4*)y)[idx*2 + 1] = v1;
}

// ---------------- launcher ---------------------------------------------------------------
extern "C" void kernel_launch(void* const* d_in, const int* in_sizes, int n_in,
                              void* d_out, int out_size) {
    const float* x      = (const float*)d_in[0];
    const float* fc_w   = (const float*)d_in[1];
    const float* fc_b   = (const float*)d_in[2];
    const float* weight = (const float*)d_in[3];
    const float* bias   = (const float*)d_in[4];
    const float* gamma  = (const float*)d_in[5];
    const float* beta   = (const float*)d_in[6];
    float* y = (float*)d_out;

    cudaFuncSetAttribute(conv_mma_kernel,
                         cudaFuncAttributeMaxDynamicSharedMemorySize, CONV_SMEM);

    dim3 tgrid(WW_/32, HH_, B_);
    xT_kernel<<<tgrid, 256>>>(x, fc_w, fc_b, bias);

    wmix_kernel<<<C2_, 256>>>(weight);

    dim3 cgrid(24, B_);
    conv_mma_kernel<<<cgrid, 256, CONV_SMEM>>>();

    bnfin_kernel<<<C2_, 256>>>(gamma, beta);

    const int N8 = (B_*C2_*HW_) / 8;
    act_kernel<<<(N8 + 255)/256, 256>>>(y);
}